// round 9
// baseline (speedup 1.0000x reference)
#include <cuda_runtime.h>

// NbitTreeDecoder R9: one thread per level-9 node (262144 threads), DENSE
// warp-level stores. A warp's 32 nodes form 96 contiguous float4; lane L at
// slot s writes float4 s*32+L, fetching the source node's packed state
// (B, rp) from lane q/3 via __shfl_sync and recomputing the 4 floats locally.
// Each STG.128 touches 4 cache lines (dense) instead of 12 (48B-stride).
//
// Identities (validated rounds 1-8, rel_err 2.9e-8):
//   Xr = brev32(X)>>2 = sum_t rev3(j_t) << 3t  (accumulated directly, no BREV)
//   x = Xr&1023, y = (Xr>>10)&1023 per node; z-field = (B>>20) | (rev3(j9)<<7)
//   float(field) = __uint_as_float(0x4B000000|field) - 2^23   (exact)

#define MAGIC  0x4B000000u
#define MAGICF 8388608.0f

static __device__ __forceinline__ unsigned nth_set_bit(unsigned f, unsigned d) {
    unsigned g = f;
    g = (d > 0u) ? (g & (g - 1u)) : g;
    g = (d > 1u) ? (g & (g - 1u)) : g;
    g = (d > 2u) ? (g & (g - 1u)) : g;
    return (unsigned)__ffs(g) - 1u;
}

static __device__ __forceinline__ unsigned rev3(unsigned j) {
    return ((j & 1u) << 2) | (j & 2u) | ((j >> 2) & 1u);
}

__global__ void __launch_bounds__(256)
decode_kernel(const int* __restrict__ flags,
              const float* __restrict__ offset,
              const float* __restrict__ scale,
              float* __restrict__ out)
{
    const unsigned tid  = threadIdx.x;
    const unsigned n9   = blockIdx.x * 256u + tid;   // this thread's level-9 node
    const unsigned n8   = n9 >> 2;
    const unsigned lane = tid & 31u;

    // ---- all global loads up front (addresses depend only on thread id) ----
    const unsigned OFF[8] = {0u, 1u, 5u, 21u, 85u, 341u, 1365u, 5461u};
    unsigned fl[8];
#pragma unroll
    for (int t = 0; t < 8; t++)
        fl[t] = (unsigned)__ldg(flags + OFF[t] + (n9 >> (18 - 2 * t)));
    const unsigned f8 = (unsigned)__ldg(flags + 21845u + n8);
    const unsigned f9 = (unsigned)__ldg(flags + 87381u + n9);

    const float2 s01 = __ldg(reinterpret_cast<const float2*>(scale));
    const float  s2  = __ldg(scale + 2);
    const float2 o01 = __ldg(reinterpret_cast<const float2*>(offset));
    const float  o2  = __ldg(offset + 2);

    // ---- build reversed code B directly: levels 0..7 then level 8 ----
    unsigned B = 0u;
#pragma unroll
    for (int t = 0; t < 8; t++) {
        const unsigned d = (n9 >> (16 - 2 * t)) & 3u;
        B |= rev3(nth_set_bit(fl[t], d)) << (3 * t);
    }
    B |= rev3(nth_set_bit(f8, n9 & 3u)) << 24;       // 27-bit reversed prefix

    // ---- packed rev3 of the level-9 flag's 4 set bits (4-bit slots) ----
    unsigned rp = 0u, g = f9;
#pragma unroll
    for (int d = 0; d < 4; d++) {
        const unsigned j = (unsigned)__ffs(g) - 1u;  g &= g - 1u;
        rp |= rev3(j) << (4 * d);
    }

    // ---- dense stores: warp writes its 96 contiguous float4 ----
    // node float layout: [x,y,z0, x,y,z1, x,y,z2, x,y,z3]  (3 float4 pieces)
    float4* outw = reinterpret_cast<float4*>(out) + 3u * (n9 & ~31u);

#pragma unroll
    for (unsigned s = 0; s < 3; s++) {
        const unsigned q   = s * 32u + lane;         // float4 index in warp region
        const unsigned src = q / 3u;                 // source lane (node owner)
        const unsigned p   = q - 3u * src;           // piece 0..2
        const unsigned Bs  = __shfl_sync(0xffffffffu, B,  (int)src);
        const unsigned rps = __shfl_sync(0xffffffffu, rp, (int)src);

        const float x = fmaf(__uint_as_float(MAGIC | (Bs & 1023u)) - MAGICF, s01.x, o01.x);
        const float y = fmaf(__uint_as_float(MAGIC | ((Bs >> 10) & 1023u)) - MAGICF, s01.y, o01.y);
        const unsigned M2 = MAGIC | (Bs >> 20);
        const float za = fmaf(__uint_as_float(M2 | (((rps >> (4u * p)) & 7u) << 7)) - MAGICF, s2, o2);
        const float zb = fmaf(__uint_as_float(M2 | (((rps >> 12) & 7u) << 7)) - MAGICF, s2, o2);

        // piece 0: (x,y,z0,x)   piece 1: (y,z1,x,y)   piece 2: (z2,x,y,z3)
        float c0, c1, c2, c3;
        if (p == 0u)      { c0 = x;  c1 = y;  c2 = za; c3 = x;  }
        else if (p == 1u) { c0 = y;  c1 = za; c2 = x;  c3 = y;  }
        else              { c0 = za; c1 = x;  c2 = y;  c3 = zb; }

        outw[q] = make_float4(c0, c1, c2, c3);
    }
}

extern "C" void kernel_launch(void* const* d_in, const int* in_sizes, int n_in,
                              void* d_out, int out_size) {
    const int*   flags  = (const int*)d_in[0];
    const float* offset = (const float*)d_in[1];
    const float* scale  = (const float*)d_in[2];
    float*       out    = (float*)d_out;

    decode_kernel<<<1024, 256>>>(flags, offset, scale, out);
}